// round 8
// baseline (speedup 1.0000x reference)
#include <cuda_runtime.h>

// Problem constants (T=4, B=1, C=256, N=1024, H=16, D=16)
#define T_   4
#define C_   256
#define N_   1024
#define M_   4          // T*B
#define H_   16
#define D_   16
#define CN   (C_*N_)    // 262144
#define TOT  (M_*C_*N_) // 1048576
#define EPSV 1e-5f

// ---------------- scratch (device globals; allocation-free) ----------------
__device__ float    g_h[3][TOT];       // q/k/v pre-BN activations (12 MiB)
__device__ float    g_p[TOT];          // proj pre-BN activations (4 MiB)
__device__ float    g_s2[TOT];         // attn-lif output as {0,1} fp32 (4 MiB)
__device__ float    g_mean[4*C_];      // per-channel mean  (z=0..2 branches, z=3 proj)
__device__ float    g_istd[4*C_];      // per-channel 1/sqrt(var+eps)
__device__ unsigned g_qbits[M_*H_*N_]; // q spikes: d-mask per (m,h,n)
__device__ unsigned g_bitsT[2*64*16*32]; // k/v transposed: [z][th][d][n_word]
__device__ float    g_partS[4*C_*32];  // per-(channel, colTile) partial sums
__device__ float    g_partQ[4*C_*32];  // per-(channel, colTile) partial sumsq

// ---------------- f32x2 helpers (FFMA2: exact dual fp32 FMA) ----------------
__device__ __forceinline__ unsigned long long dup2(float v) {
    unsigned long long r; unsigned u = __float_as_uint(v);
    asm("mov.b64 %0, {%1, %1};" : "=l"(r) : "r"(u));
    return r;
}
#define FFMA2(acc, a, b) \
    asm("fma.rn.f32x2 %0, %1, %2, %0;" : "+l"(acc) : "l"(a), "l"(b))
#define UNPACK2(lo, hi, v) \
    asm("mov.b64 {%0, %1}, %2;" : "=f"(lo), "=f"(hi) : "l"(v))

// ---------------- GEMM body: O[m,o,n] = sum_c W[o,c] * X[m,c,n] -------------
// BM=64, BN=128, BK=16, 256 threads, 4x8 register tile per thread (f32x2).
// Epilogue also emits per-channel (sum, sumsq) partials for BN stats.
__device__ __forceinline__ void gemm_body(const float* __restrict__ W,
                                          const float* __restrict__ X,
                                          float* __restrict__ O,
                                          float* __restrict__ partS,
                                          float* __restrict__ partQ)
{
    __shared__ unsigned long long As2[16][68];  // [k][o] duplicated pairs, padded
    __shared__ float Bs[16][128];               // [k][n]

    const int tid     = threadIdx.x;
    const int colTile = blockIdx.x;          // 0..31  (4096 cols / 128)
    const int m       = colTile >> 3;        // 8 col tiles per m (1024/128)
    const int n0      = (colTile & 7) << 7;
    const int o0      = blockIdx.y << 6;     // 4 row tiles (C=256 / 64)
    const int ty      = tid >> 4;            // 0..15 -> 4 rows each
    const int tx      = tid & 15;            // 0..15 -> 8 cols each

    const int lo_o = tid >> 2;               // As: 0..63
    const int lo_c = (tid & 3) << 2;         // As: 0,4,8,12
    const int lb_c = tid >> 4;               // Bs: 0..15
    const int lb_n = (tid & 15) << 3;        // Bs: 0..120 step 8

    unsigned long long acc[4][4];            // 4 rows x 4 f32x2 pairs (8 cols)
    #pragma unroll
    for (int i = 0; i < 4; ++i)
        #pragma unroll
        for (int j = 0; j < 4; ++j) acc[i][j] = 0ull;

    for (int k0 = 0; k0 < C_; k0 += 16) {
        {
            float4 wv = *(const float4*)&W[(o0 + lo_o) * C_ + k0 + lo_c];
            As2[lo_c + 0][lo_o] = dup2(wv.x);
            As2[lo_c + 1][lo_o] = dup2(wv.y);
            As2[lo_c + 2][lo_o] = dup2(wv.z);
            As2[lo_c + 3][lo_o] = dup2(wv.w);
        }
        {
            const float* src = &X[m * CN + (k0 + lb_c) * N_ + n0 + lb_n];
            float4 x0 = *(const float4*)(src);
            float4 x1 = *(const float4*)(src + 4);
            *(float4*)&Bs[lb_c][lb_n]     = x0;
            *(float4*)&Bs[lb_c][lb_n + 4] = x1;
        }
        __syncthreads();

        #pragma unroll
        for (int k = 0; k < 16; ++k) {
            ulonglong2 a01 = *(const ulonglong2*)&As2[k][ty * 4];
            ulonglong2 a23 = *(const ulonglong2*)&As2[k][ty * 4 + 2];
            unsigned long long ap[4] = { a01.x, a01.y, a23.x, a23.y };
            ulonglong2 b01 = *(const ulonglong2*)&Bs[k][tx * 8];
            ulonglong2 b23 = *(const ulonglong2*)&Bs[k][tx * 8 + 4];
            unsigned long long bp[4] = { b01.x, b01.y, b23.x, b23.y };
            #pragma unroll
            for (int i = 0; i < 4; ++i) {
                FFMA2(acc[i][0], ap[i], bp[0]);
                FFMA2(acc[i][1], ap[i], bp[1]);
                FFMA2(acc[i][2], ap[i], bp[2]);
                FFMA2(acc[i][3], ap[i], bp[3]);
            }
        }
        __syncthreads();
    }

    // store output + per-channel stats partials
    #pragma unroll
    for (int i = 0; i < 4; ++i) {
        float* dst = &O[m * CN + (o0 + ty * 4 + i) * N_ + n0 + tx * 8];
        ulonglong2 s0, s1;
        s0.x = acc[i][0]; s0.y = acc[i][1];
        s1.x = acc[i][2]; s1.y = acc[i][3];
        *(ulonglong2*)(dst)     = s0;
        *(ulonglong2*)(dst + 4) = s1;

        float s = 0.0f, q2 = 0.0f;
        #pragma unroll
        for (int j = 0; j < 4; ++j) {
            float lo, hi;
            UNPACK2(lo, hi, acc[i][j]);
            s  += lo + hi;
            q2 += lo * lo + hi * hi;
        }
        #pragma unroll
        for (int off = 8; off > 0; off >>= 1) {
            s  += __shfl_down_sync(0xFFFFFFFFu, s,  off, 16);
            q2 += __shfl_down_sync(0xFFFFFFFFu, q2, off, 16);
        }
        if (tx == 0) {
            int c = o0 + ty * 4 + i;
            partS[c * 32 + colTile] = s;
            partQ[c * 32 + colTile] = q2;
        }
    }
}

// Branch GEMMs: z=0 -> Wq@x, z=1 -> Wk@y, z=2 -> Wv@y
__global__ void __launch_bounds__(256)
gemm_branch(const float* __restrict__ x, const float* __restrict__ y,
            const float* __restrict__ Wq, const float* __restrict__ Wk,
            const float* __restrict__ Wv)
{
    const int z = blockIdx.z;
    const float* W = (z == 0) ? Wq : (z == 1) ? Wk : Wv;
    const float* X = (z == 0) ? x : y;
    gemm_body(W, X, g_h[z], &g_partS[z * C_ * 32], &g_partQ[z * C_ * 32]);
}

// Proj GEMM: g_p = Wp @ g_s2
__global__ void __launch_bounds__(256)
gemm_proj(const float* __restrict__ Wp)
{
    gemm_body(Wp, g_s2, g_p, &g_partS[3 * C_ * 32], &g_partQ[3 * C_ * 32]);
}

// ---------------- stats finalize: reduce 32 partials per channel ------------
// mode 0: grid (C_,3) for branches; mode 1: grid (C_,1) for proj. 32 threads.
__global__ void __launch_bounds__(32)
finalize_kernel(int mode)
{
    const int c = blockIdx.x;
    const int sidx = (mode == 0) ? blockIdx.y * C_ + c : 3 * C_ + c;
    const int lane = threadIdx.x;
    float s = g_partS[sidx * 32 + lane];
    float q = g_partQ[sidx * 32 + lane];
    #pragma unroll
    for (int off = 16; off > 0; off >>= 1) {
        s += __shfl_down_sync(0xFFFFFFFFu, s, off);
        q += __shfl_down_sync(0xFFFFFFFFu, q, off);
    }
    if (lane == 0) {
        float mean = s * (1.0f / 4096.0f);
        float var  = q * (1.0f / 4096.0f) - mean * mean;
        g_mean[sidx] = mean;
        g_istd[sidx] = rsqrtf(var + EPSV);
    }
}

// ---------------- BN + LIF spike + pack (vth = 1.0) -------------------------
// z=0 (q): store d-mask per (m,h,n). z=1,2 (k,v): ballot-transpose, store
// n-major words g_bitsT[z-1][th][d][n>>5].
__global__ void __launch_bounds__(256)
pack_kernel(const float* __restrict__ gq, const float* __restrict__ bq,
            const float* __restrict__ gk, const float* __restrict__ bk,
            const float* __restrict__ gv, const float* __restrict__ bv)
{
    const int z   = blockIdx.y;
    const int idx = blockIdx.x * 256 + threadIdx.x;  // (m,h,n), n fastest
    const int lane = threadIdx.x & 31;
    const int n = idx & 1023;
    const int h = (idx >> 10) & 15;
    const int m = idx >> 14;
    const float* G  = (z == 0) ? gq : (z == 1) ? gk : gv;
    const float* Bt = (z == 0) ? bq : (z == 1) ? bk : bv;
    const float* Hs = g_h[z];

    unsigned mask = 0;
    unsigned myword = 0;
    #pragma unroll
    for (int d = 0; d < 16; ++d) {
        int c = h * 16 + d;
        float xv = Hs[m * CN + c * N_ + n];
        float bn = G[c] * (xv - g_mean[z * C_ + c]) * g_istd[z * C_ + c] + Bt[c];
        bool sp = (bn >= 1.0f);
        if (sp) mask |= (1u << d);
        if (z != 0) {
            unsigned bal = __ballot_sync(0xFFFFFFFFu, sp);
            if (lane == d) myword = bal;
        }
    }
    if (z == 0) {
        g_qbits[idx] = mask;
    } else if (lane < 16) {
        const int th = m * 16 + h;
        const int chunk = (n >> 5);          // 0..31
        g_bitsT[((z - 1) * 64 + th) * 512 + lane * 32 + chunk] = myword;
    }
}

// ---------------- fused attention: s2 = ( q (k^T v) * 0.25 >= 0.5 ) ---------
// Exact integer path: G[d1][d2] = popc-sum over n-words; spike <=> sum >= 2.
// grid = 64 th * 4 n-chunks of 256.
__global__ void __launch_bounds__(256)
attn_kernel()
{
    __shared__ unsigned Ktr[16 * 33];   // [d][w] padded (33) -> conflict-free
    __shared__ unsigned Vtr[16 * 33];
    __shared__ int Gs[256];

    const int bid   = blockIdx.x;
    const int th    = bid >> 2;
    const int chunk = bid & 3;
    const int tid   = threadIdx.x;

    // load transposed K and V words (512 each)
    {
        const unsigned* Kg = &g_bitsT[(0 * 64 + th) * 512];
        const unsigned* Vg = &g_bitsT[(1 * 64 + th) * 512];
        #pragma unroll
        for (int i = tid; i < 512; i += 256) {
            int d = i >> 5, w = i & 31;
            Ktr[d * 33 + w] = Kg[i];
            Vtr[d * 33 + w] = Vg[i];
        }
    }
    __syncthreads();

    // G[d1][d2]: one (d1,d2) pair per thread, 32 popc(AND)
    {
        const int d1 = tid >> 4, d2 = tid & 15;
        int cnt = 0;
        #pragma unroll
        for (int w = 0; w < 32; ++w)
            cnt += __popc(Ktr[d1 * 33 + w] & Vtr[d2 * 33 + w]);
        Gs[tid] = cnt;
    }
    __syncthreads();

    // apply to q: one n per thread
    const int n = chunk * 256 + tid;
    const unsigned q = g_qbits[(th << 10) + n];
    int acc[16];
    #pragma unroll
    for (int d = 0; d < 16; ++d) acc[d] = 0;
    #pragma unroll
    for (int d1 = 0; d1 < 16; ++d1) {
        const int msk = -(int)((q >> d1) & 1u);
        #pragma unroll
        for (int d = 0; d < 16; ++d)
            acc[d] += Gs[d1 * 16 + d] & msk;
    }

    const int t = th >> 4, h = th & 15;
    #pragma unroll
    for (int d = 0; d < 16; ++d)
        g_s2[t * CN + (h * 16 + d) * N_ + n] = (acc[d] >= 2) ? 1.0f : 0.0f;
}

// ---------------- final proj BN + spike (vth = 1.0) -> output ---------------
__global__ void __launch_bounds__(256)
final_kernel(const float* __restrict__ gp, const float* __restrict__ bp,
             float* __restrict__ out)
{
    const int idx = blockIdx.x * 256 + threadIdx.x;   // 0..TOT-1
    const int c = (idx >> 10) & 255;
    float xv = g_p[idx];
    float bn = gp[c] * (xv - g_mean[3 * C_ + c]) * g_istd[3 * C_ + c] + bp[c];
    out[idx] = (bn >= 1.0f) ? 1.0f : 0.0f;
}

// ---------------- launcher --------------------------------------------------
extern "C" void kernel_launch(void* const* d_in, const int* in_sizes, int n_in,
                              void* d_out, int out_size)
{
    const float* x  = (const float*)d_in[0];
    const float* y  = (const float*)d_in[1];
    const float* Wq = (const float*)d_in[2];
    const float* gq = (const float*)d_in[3];
    const float* bq = (const float*)d_in[4];
    const float* Wk = (const float*)d_in[5];
    const float* gk = (const float*)d_in[6];
    const float* bk = (const float*)d_in[7];
    const float* Wv = (const float*)d_in[8];
    const float* gv = (const float*)d_in[9];
    const float* bv = (const float*)d_in[10];
    const float* Wp = (const float*)d_in[11];
    const float* gp = (const float*)d_in[12];
    const float* bp = (const float*)d_in[13];
    float* out = (float*)d_out;

    gemm_branch<<<dim3(32, 4, 3), 256>>>(x, y, Wq, Wk, Wv);
    finalize_kernel<<<dim3(C_, 3), 32>>>(0);
    pack_kernel<<<dim3(256, 3), 256>>>(gq, bq, gk, bk, gv, bv);
    attn_kernel<<<256, 256>>>();
    gemm_proj<<<dim3(32, 4, 1), 256>>>(Wp);
    finalize_kernel<<<dim3(C_, 1), 32>>>(1);
    final_kernel<<<TOT / 256, 256>>>(gp, bp, out);
}